// round 1
// baseline (speedup 1.0000x reference)
#include <cuda_runtime.h>

#define BS 32
#define NN 200
#define HD 100
#define NH 34
#define SDIM 1024
#define NRH (NN*HD)   // 20000
#define EPSV 1e-20f

// ---------------- scratch (device globals; no allocation) ----------------
__device__ float g_Y[(size_t)BS*NH*NRH];    // 87 MB  (Y0 then Y1)
__device__ float g_Zh[(size_t)BS*NH*NRH];   // 87 MB  (Zh0 then Zh1)
__device__ float g_Ztr[(size_t)BS*NH*NRH];  // 87 MB  (Zsum temp, then Ztr)
__device__ float g_dvec[BS*NH*NN];
__device__ float g_D[BS*NH*NN];
__device__ float g_Zt[2*BS*NRH];
__device__ float g_Dt[2*BS*NN];
__device__ float g_Sq[BS*HD];

// ---------------- Sq = S @ wq_w^T + wq_b ----------------
__global__ void k_sq(const float* __restrict__ S, const float* __restrict__ wqw,
                     const float* __restrict__ wqb)
{
    int lane = threadIdx.x & 31;
    int gw = blockIdx.x * 8 + (threadIdx.x >> 5);
    if (gw >= BS*HD) return;
    int b = gw / HD, h = gw % HD;
    const float* sp = S + (size_t)b * SDIM;
    const float* wp = wqw + (size_t)h * SDIM;
    float acc = 0.f;
    for (int k = lane * 4; k < SDIM; k += 128) {
        float4 s4 = *(const float4*)(sp + k);
        float4 w4 = *(const float4*)(wp + k);
        acc += s4.x*w4.x + s4.y*w4.y + s4.z*w4.z + s4.w*w4.w;
    }
    #pragma unroll
    for (int o = 16; o > 0; o >>= 1) acc += __shfl_down_sync(0xffffffffu, acc, o);
    if (lane == 0) g_Sq[b*HD + h] = acc + wqb[h];
}

// ---------------- dvec0[b,r,j] = start[b,j]*uni[b,r] ----------------
__global__ void k_dvec0(const float* __restrict__ start, const float* __restrict__ uni)
{
    int idx = blockIdx.x * 256 + threadIdx.x;
    if (idx >= BS*NH*NN) return;
    int b = idx / (NH*NN);
    int rem = idx - b*(NH*NN);
    int r = rem / NN, j = rem - r*NN;
    g_dvec[idx] = start[b*NN + j] * uni[b*NH + r];
}

// ---------------- dvec1[b,s,j] = uni[b,s]*sum_r D0[b,r,j]*trans[b,r,s] ----------------
__global__ void k_dvec1(const float* __restrict__ uni, const float* __restrict__ trans)
{
    int idx = blockIdx.x * 256 + threadIdx.x;
    if (idx >= BS*NH*NN) return;
    int b = idx / (NH*NN);
    int rem = idx - b*(NH*NN);
    int s = rem / NN, j = rem - s*NN;
    float acc = 0.f;
    #pragma unroll 2
    for (int r = 0; r < NH; ++r)
        acc += g_D[(b*NH + r)*NN + j] * trans[(b*NH + r)*NH + s];
    g_dvec[idx] = uni[b*NH + s] * acc;
}

// ---------------- generic 200xK x Kx100 GEMM (modes) ----------------
// mode 0: Y0   = rowscale(start)*uni * (X[b] @ W0[r])      grid (34, 32)
// mode 1: Y1   = uni * (Ztr[b,s] @ W1[s])                  grid (34, 32)
// mode 2: Zt0  = rowscale(end) * (Zsum[b] @ Wpad)          grid (1, 32)
__global__ void k_gemm(int mode, const float* __restrict__ X,
                       const float* __restrict__ wvs,
                       const float* __restrict__ uni,
                       const float* __restrict__ start,
                       const float* __restrict__ endv)
{
    int b = blockIdx.y, r = blockIdx.x;
    const float* In; const float* W; const float* rs; float cscale; float* Out;
    if (mode == 0) {
        In = X + (size_t)b * NRH;
        W = wvs + (size_t)r * (HD*HD);
        cscale = uni[b*NH + r];
        rs = start + b*NN;
        Out = g_Y + (size_t)(b*NH + r) * NRH;
    } else if (mode == 1) {
        In = g_Ztr + (size_t)(b*NH + r) * NRH;
        W = wvs + (size_t)(35 + r) * (HD*HD);
        cscale = uni[b*NH + r];
        rs = nullptr;
        Out = g_Y + (size_t)(b*NH + r) * NRH;
    } else {
        In = g_Ztr + (size_t)b * NRH;          // Zsum temp
        W = wvs + (size_t)69 * (HD*HD);        // w_vs[1,34] = W_pad[0]
        cscale = 1.0f;
        rs = endv + b*NN;
        Out = g_Zt + (size_t)b * NRH;          // t=0 slot
    }

    __shared__ float As[128][33];
    __shared__ float Bs[32][128];
    int tid = threadIdx.x;
    int tx = tid & 15, ty = tid >> 4;

    for (int mt = 0; mt < 2; ++mt) {
        float acc[8][8];
        #pragma unroll
        for (int i = 0; i < 8; ++i)
            #pragma unroll
            for (int j = 0; j < 8; ++j) acc[i][j] = 0.f;

        for (int k0 = 0; k0 < HD; k0 += 32) {
            int klen = min(32, HD - k0);
            // load A tile 128x32 (zero-padded)
            #pragma unroll
            for (int l = 0; l < 4; ++l) {
                int idx = tid + l*256;
                int row = idx >> 3;
                int c4 = (idx & 7) << 2;
                int grow = mt*128 + row;
                float4 v = make_float4(0.f,0.f,0.f,0.f);
                if (grow < NN && c4 < klen)
                    v = *(const float4*)(In + (size_t)grow*HD + k0 + c4);
                As[row][c4+0] = v.x; As[row][c4+1] = v.y;
                As[row][c4+2] = v.z; As[row][c4+3] = v.w;
            }
            // load B tile 32x128 (cols >=100 zero)
            #pragma unroll
            for (int l = 0; l < 4; ++l) {
                int idx = tid + l*256;
                int kk = idx >> 5;
                int c4 = (idx & 31) << 2;
                float4 v = make_float4(0.f,0.f,0.f,0.f);
                if (kk < klen && c4 < HD)
                    v = *(const float4*)(W + (size_t)(k0+kk)*HD + c4);
                *(float4*)&Bs[kk][c4] = v;
            }
            __syncthreads();
            #pragma unroll 4
            for (int kk = 0; kk < klen; ++kk) {
                float a[8];
                #pragma unroll
                for (int i = 0; i < 8; ++i) a[i] = As[ty*8 + i][kk];
                float4 b0 = *(float4*)&Bs[kk][tx*8];
                float4 b1 = *(float4*)&Bs[kk][tx*8 + 4];
                float bb[8] = {b0.x,b0.y,b0.z,b0.w,b1.x,b1.y,b1.z,b1.w};
                #pragma unroll
                for (int i = 0; i < 8; ++i)
                    #pragma unroll
                    for (int j = 0; j < 8; ++j)
                        acc[i][j] += a[i] * bb[j];
            }
            __syncthreads();
        }
        #pragma unroll
        for (int i = 0; i < 8; ++i) {
            int grow = mt*128 + ty*8 + i;
            if (grow < NN) {
                float sc = cscale * (rs ? rs[grow] : 1.0f);
                #pragma unroll
                for (int j = 0; j < 8; ++j) {
                    int c = tx*8 + j;
                    if (c < HD) Out[(size_t)grow*HD + c] = acc[i][j] * sc;
                }
            }
        }
    }
}

// ---------------- Zh[b,r] = A[b,r] @ Y[b,r] (+dvec as col 100 -> D) ----------------
__global__ void k_agemm(const float* __restrict__ A)
{
    int b = blockIdx.y, r = blockIdx.x;
    const float* Ab = A + (size_t)(b*NH + r) * NN * NN;
    const float* Yb = g_Y + (size_t)(b*NH + r) * NRH;
    const float* db = g_dvec + (b*NH + r) * NN;
    float* Zb = g_Zh + (size_t)(b*NH + r) * NRH;
    float* Db = g_D + (b*NH + r) * NN;

    __shared__ float As[128][33];
    __shared__ float Ys[32][128];
    int tid = threadIdx.x;
    int tx = tid & 15, ty = tid >> 4;

    for (int mt = 0; mt < 2; ++mt) {
        float acc[8][8];
        #pragma unroll
        for (int i = 0; i < 8; ++i)
            #pragma unroll
            for (int j = 0; j < 8; ++j) acc[i][j] = 0.f;

        for (int k0 = 0; k0 < NN; k0 += 32) {
            int klen = min(32, NN - k0);
            #pragma unroll
            for (int l = 0; l < 4; ++l) {
                int idx = tid + l*256;
                int row = idx >> 3;
                int c4 = (idx & 7) << 2;
                int grow = mt*128 + row;
                float4 v = make_float4(0.f,0.f,0.f,0.f);
                if (grow < NN && c4 < klen)
                    v = *(const float4*)(Ab + (size_t)grow*NN + k0 + c4);
                As[row][c4+0] = v.x; As[row][c4+1] = v.y;
                As[row][c4+2] = v.z; As[row][c4+3] = v.w;
            }
            #pragma unroll
            for (int l = 0; l < 4; ++l) {
                int idx = tid + l*256;
                int kk = idx >> 5;
                int c4 = (idx & 31) << 2;
                float4 v = make_float4(0.f,0.f,0.f,0.f);
                if (kk < klen) {
                    int gk = k0 + kk;
                    if (c4 < HD)       v = *(const float4*)(Yb + (size_t)gk*HD + c4);
                    else if (c4 == 100) v.x = db[gk];
                }
                *(float4*)&Ys[kk][c4] = v;
            }
            __syncthreads();
            #pragma unroll 4
            for (int kk = 0; kk < klen; ++kk) {
                float a[8];
                #pragma unroll
                for (int i = 0; i < 8; ++i) a[i] = As[ty*8 + i][kk];
                float4 b0 = *(float4*)&Ys[kk][tx*8];
                float4 b1 = *(float4*)&Ys[kk][tx*8 + 4];
                float bb[8] = {b0.x,b0.y,b0.z,b0.w,b1.x,b1.y,b1.z,b1.w};
                #pragma unroll
                for (int i = 0; i < 8; ++i)
                    #pragma unroll
                    for (int j = 0; j < 8; ++j)
                        acc[i][j] += a[i] * bb[j];
            }
            __syncthreads();
        }
        #pragma unroll
        for (int i = 0; i < 8; ++i) {
            int grow = mt*128 + ty*8 + i;
            if (grow < NN) {
                #pragma unroll
                for (int j = 0; j < 8; ++j) {
                    int c = tx*8 + j;
                    if (c < HD)        Zb[(size_t)grow*HD + c] = acc[i][j];
                    else if (c == 100) Db[grow] = acc[i][j];
                }
            }
        }
    }
}

// ---------------- Zsum[b,x] = sum_r Zh0[b,r,x]  (into g_Ztr[b*NRH]) ----------------
__global__ void k_rsum()
{
    int x = blockIdx.x * 256 + threadIdx.x;
    int b = blockIdx.y;
    if (x >= NRH) return;
    float acc = 0.f;
    #pragma unroll 2
    for (int r = 0; r < NH; ++r)
        acc += g_Zh[(size_t)(b*NH + r) * NRH + x];
    g_Ztr[(size_t)b * NRH + x] = acc;
}

// ---------------- Ztr[b,s,j,d] = sum_r Zh0[b,r,j,d]*trans[b,r,s] ----------------
__global__ void k_trans(const float* __restrict__ trans)
{
    int b = blockIdx.y;
    __shared__ float ts[NH*NH];
    for (int i = threadIdx.x; i < NH*NH; i += 256) ts[i] = trans[b*NH*NH + i];
    __syncthreads();

    int x0 = blockIdx.x * 512 + threadIdx.x;   // two elements: x0, x0+256
    const float* Zb = g_Zh + (size_t)b * NH * NRH;
    float acc0[NH], acc1[NH];
    #pragma unroll
    for (int s = 0; s < NH; ++s) { acc0[s] = 0.f; acc1[s] = 0.f; }

    for (int r = 0; r < NH; ++r) {
        float v0 = (x0 < NRH)       ? Zb[(size_t)r*NRH + x0]       : 0.f;
        float v1 = (x0 + 256 < NRH) ? Zb[(size_t)r*NRH + x0 + 256] : 0.f;
        #pragma unroll
        for (int s = 0; s < NH; ++s) {
            float tv = ts[r*NH + s];
            acc0[s] += v0 * tv;
            acc1[s] += v1 * tv;
        }
    }
    float* Ztb = g_Ztr + (size_t)b * NH * NRH;
    #pragma unroll
    for (int s = 0; s < NH; ++s) {
        if (x0 < NRH)       Ztb[(size_t)s*NRH + x0] = acc0[s];
        if (x0 + 256 < NRH) Ztb[(size_t)s*NRH + x0 + 256] = acc1[s];
    }
}

// ---------------- Zt1[b,x] = end[b,i] * sum_r Zh1[b,r,x] ----------------
__global__ void k_zt1(const float* __restrict__ endv)
{
    int x = blockIdx.x * 256 + threadIdx.x;
    int b = blockIdx.y;
    if (x >= NRH) return;
    float acc = 0.f;
    #pragma unroll 2
    for (int r = 0; r < NH; ++r)
        acc += g_Zh[(size_t)(b*NH + r) * NRH + x];
    int i = x / HD;
    g_Zt[(size_t)(BS + b) * NRH + x] = acc * endv[b*NN + i];
}

// ---------------- Dt[t][b,i] = end * sum_r D[b,r,i] ----------------
__global__ void k_dt(int t, const float* __restrict__ endv)
{
    int idx = blockIdx.x * 256 + threadIdx.x;
    if (idx >= BS*NN) return;
    int b = idx / NN, i = idx - b*NN;
    float acc = 0.f;
    #pragma unroll 2
    for (int r = 0; r < NH; ++r) acc += g_D[(b*NH + r)*NN + i];
    g_Dt[t*BS*NN + idx] = acc * endv[idx];
}

// ---------------- epilogue: normalize, attn, softmax(K=2), combine ----------------
__global__ void k_out(float* __restrict__ out)
{
    int bn = blockIdx.x;
    int b = bn / NN, n = bn - b*NN;
    int tid = threadIdx.x;
    __shared__ float red[128];

    float z[2], dt[2];
    #pragma unroll
    for (int t = 0; t < 2; ++t) {
        float zv = 0.f;
        if (tid < HD) {
            float dd = g_Dt[t*BS*NN + b*NN + n];
            zv = g_Zt[(size_t)(t*BS + b) * NRH + n*HD + tid] / (dd + EPSV);
        }
        z[t] = zv;
        red[tid] = (tid < HD) ? g_Sq[b*HD + tid] * zv : 0.f;
        __syncthreads();
        for (int s = 64; s > 0; s >>= 1) {
            if (tid < s) red[tid] += red[tid + s];
            __syncthreads();
        }
        dt[t] = red[0] * 0.1f;   // / sqrt(100)
        __syncthreads();
    }
    float m = fmaxf(dt[0], dt[1]);
    float e0 = expf(dt[0] - m), e1 = expf(dt[1] - m);
    float inv = 1.f / (e0 + e1);
    if (tid < HD)
        out[(size_t)bn * HD + tid] = (e0 * z[0] + e1 * z[1]) * inv;
}

// ---------------- launch ----------------
extern "C" void kernel_launch(void* const* d_in, const int* in_sizes, int n_in,
                              void* d_out, int out_size)
{
    (void)in_sizes; (void)n_in; (void)out_size;
    const float* X     = (const float*)d_in[0];
    const float* A     = (const float*)d_in[1];
    const float* start = (const float*)d_in[2];
    const float* endv  = (const float*)d_in[3];
    const float* uni   = (const float*)d_in[4];
    const float* trans = (const float*)d_in[5];
    const float* S     = (const float*)d_in[6];
    const float* wvs   = (const float*)d_in[7];
    const float* wqw   = (const float*)d_in[8];
    const float* wqb   = (const float*)d_in[9];
    float* out = (float*)d_out;

    // t = 0
    k_sq<<<(BS*HD + 7) / 8, 256>>>(S, wqw, wqb);
    k_dvec0<<<(BS*NH*NN + 255) / 256, 256>>>(start, uni);
    k_gemm<<<dim3(NH, BS), 256>>>(0, X, wvs, uni, start, endv);   // Y0
    k_agemm<<<dim3(NH, BS), 256>>>(A);                            // Zh0, D0
    k_dt<<<(BS*NN + 255) / 256, 256>>>(0, endv);
    k_rsum<<<dim3((NRH + 255) / 256, BS), 256>>>();               // Zsum -> g_Ztr[:BS*NRH]
    k_gemm<<<dim3(1, BS), 256>>>(2, X, wvs, uni, start, endv);    // Zt0 = Zsum @ Wpad * end
    // t = 1
    k_trans<<<dim3((NRH + 511) / 512, BS), 256>>>(trans);         // Ztr (overwrites Zsum region)
    k_dvec1<<<(BS*NH*NN + 255) / 256, 256>>>(uni, trans);
    k_gemm<<<dim3(NH, BS), 256>>>(1, X, wvs, uni, start, endv);   // Y1
    k_agemm<<<dim3(NH, BS), 256>>>(A);                            // Zh1, D1
    k_dt<<<(BS*NN + 255) / 256, 256>>>(1, endv);
    k_zt1<<<dim3((NRH + 255) / 256, BS), 256>>>(endv);
    // epilogue
    k_out<<<BS*NN, 128>>>(out);
}

// round 3
// speedup vs baseline: 1.5734x; 1.5734x over previous
#include <cuda_runtime.h>
#include <cuda_bf16.h>
#include <cstdint>

#define BS 32
#define NN 200
#define HD 100
#define NH 34
#define SDIM 1024
#define NRH (NN*HD)   // 20000
#define YW 104        // padded Y width (100 data + dvec col + 3 zero)
#define WW 104        // padded W width (100 data + 4 zero)
#define EPSV 1e-20f

// ---------------- scratch (device globals; no allocation) ----------------
__device__ __align__(16) __nv_bfloat16 g_Ab[(size_t)BS*NH*NN*NN];   // 87 MB
__device__ __align__(16) __nv_bfloat16 g_Yh[(size_t)BS*NH*NN*YW];   // 45 MB
__device__ __align__(16) __nv_bfloat16 g_Yl[(size_t)BS*NH*NN*YW];   // 45 MB
__device__ __align__(16) __nv_bfloat16 g_Trh[(size_t)BS*NH*NRH];    // 43.5 MB
__device__ __align__(16) __nv_bfloat16 g_Trl[(size_t)BS*NH*NRH];    // 43.5 MB
__device__ __align__(16) __nv_bfloat16 g_Xh[BS*NRH];
__device__ __align__(16) __nv_bfloat16 g_Xl[BS*NRH];
__device__ __align__(16) __nv_bfloat16 g_Wh[70*HD*WW];              // padded rows (208B)
__device__ __align__(16) __nv_bfloat16 g_Wl[70*HD*WW];
__device__ float g_Zh[(size_t)BS*NH*NRH];                            // 87 MB
__device__ float g_Zsum[BS*NRH];
__device__ float g_D[BS*NH*NN];
__device__ float g_Zt[2*BS*NRH];
__device__ float g_Dt[2*BS*NN];
__device__ float g_Sq[BS*HD];

// ---------------- PTX helpers ----------------
__device__ __forceinline__ uint32_t smem_u32(const void* p) {
    return (uint32_t)__cvta_generic_to_shared(p);
}
__device__ __forceinline__ void ldsm_x4(uint32_t& r0, uint32_t& r1, uint32_t& r2, uint32_t& r3, uint32_t addr) {
    asm volatile("ldmatrix.sync.aligned.m8n8.x4.shared.b16 {%0,%1,%2,%3},[%4];"
                 : "=r"(r0), "=r"(r1), "=r"(r2), "=r"(r3) : "r"(addr));
}
__device__ __forceinline__ void ldsm_x2t(uint32_t& r0, uint32_t& r1, uint32_t addr) {
    asm volatile("ldmatrix.sync.aligned.m8n8.x2.trans.shared.b16 {%0,%1},[%2];"
                 : "=r"(r0), "=r"(r1) : "r"(addr));
}
__device__ __forceinline__ void mma16816(float* c, uint32_t a0, uint32_t a1, uint32_t a2, uint32_t a3,
                                         uint32_t b0, uint32_t b1) {
    asm volatile("mma.sync.aligned.m16n8k16.row.col.f32.bf16.bf16.f32 "
                 "{%0,%1,%2,%3},{%4,%5,%6,%7},{%8,%9},{%0,%1,%2,%3};"
                 : "+f"(c[0]), "+f"(c[1]), "+f"(c[2]), "+f"(c[3])
                 : "r"(a0), "r"(a1), "r"(a2), "r"(a3), "r"(b0), "r"(b1));
}

// ---------------- conversions ----------------
__global__ void k_convA(const float* __restrict__ A)
{
    size_t i = (size_t)blockIdx.x * 256 + threadIdx.x;     // one float4 per thread
    float4 v = *(const float4*)(A + i * 4);
    __nv_bfloat162* o = (__nv_bfloat162*)(g_Ab + i * 4);
    o[0] = __floats2bfloat162_rn(v.x, v.y);
    o[1] = __floats2bfloat162_rn(v.z, v.w);
}

// X -> g_Xh/g_Xl (unpadded, width 100; only uint2-aligned loads used downstream)
__global__ void k_splitX(const float* __restrict__ src, int n)
{
    int i = blockIdx.x * 256 + threadIdx.x;
    if (i >= n) return;
    float v = src[i];
    __nv_bfloat16 h = __float2bfloat16(v);
    g_Xh[i] = h;
    g_Xl[i] = __float2bfloat16(v - __bfloat162float(h));
}

// w_vs -> g_Wh/g_Wl padded [70][100][104] (cols 100..103 zero)
__global__ void k_splitW(const float* __restrict__ wvs)
{
    int i = blockIdx.x * 256 + threadIdx.x;   // index over padded layout
    if (i >= 70*HD*WW) return;
    int col = i % WW;
    int row = i / WW;                          // 0..70*100-1 (matrix*100 + k)
    float v = 0.f;
    if (col < HD) v = wvs[(size_t)row * HD + col];
    __nv_bfloat16 h = __float2bfloat16(v);
    g_Wh[i] = h;
    g_Wl[i] = __float2bfloat16(v - __bfloat162float(h));
}

// ---------------- Sq = S @ wq_w^T + wq_b ----------------
__global__ void k_sq(const float* __restrict__ S, const float* __restrict__ wqw,
                     const float* __restrict__ wqb)
{
    int lane = threadIdx.x & 31;
    int gw = blockIdx.x * 8 + (threadIdx.x >> 5);
    if (gw >= BS*HD) return;
    int b = gw / HD, h = gw % HD;
    const float* sp = S + (size_t)b * SDIM;
    const float* wp = wqw + (size_t)h * SDIM;
    float acc = 0.f;
    for (int k = lane * 4; k < SDIM; k += 128) {
        float4 s4 = *(const float4*)(sp + k);
        float4 w4 = *(const float4*)(wp + k);
        acc += s4.x*w4.x + s4.y*w4.y + s4.z*w4.z + s4.w*w4.w;
    }
    #pragma unroll
    for (int o = 16; o > 0; o >>= 1) acc += __shfl_down_sync(0xffffffffu, acc, o);
    if (lane == 0) g_Sq[b*HD + h] = acc + wqb[h];
}

// ---------------- dvec writers (col 100 of Yh/Yl) ----------------
__global__ void k_dvec0b(const float* __restrict__ start, const float* __restrict__ uni)
{
    int idx = blockIdx.x * 256 + threadIdx.x;
    if (idx >= BS*NH*NN) return;
    int b = idx / (NH*NN);
    int rem = idx - b*(NH*NN);
    int r = rem / NN, j = rem - r*NN;
    float v = start[b*NN + j] * uni[b*NH + r];
    size_t o = ((size_t)(b*NH + r)*NN + j)*YW + HD;
    __nv_bfloat16 h = __float2bfloat16(v);
    g_Yh[o] = h; g_Yl[o] = __float2bfloat16(v - __bfloat162float(h));
}

__global__ void k_dvec1b(const float* __restrict__ uni, const float* __restrict__ trans)
{
    int idx = blockIdx.x * 256 + threadIdx.x;
    if (idx >= BS*NH*NN) return;
    int b = idx / (NH*NN);
    int rem = idx - b*(NH*NN);
    int s = rem / NN, j = rem - s*NN;
    float acc = 0.f;
    #pragma unroll 2
    for (int r = 0; r < NH; ++r)
        acc += g_D[(b*NH + r)*NN + j] * trans[(b*NH + r)*NH + s];
    float v = uni[b*NH + s] * acc;
    size_t o = ((size_t)(b*NH + s)*NN + j)*YW + HD;
    __nv_bfloat16 h = __float2bfloat16(v);
    g_Yh[o] = h; g_Yl[o] = __float2bfloat16(v - __bfloat162float(h));
}

// ---------------- tensor-core Y GEMM ----------------
// mode 0: Y = rowscale(start)*uni * (X[b] @ W0[r]),  A-op = Xh/Xl (split)
// mode 1: Y = uni * (Ztr[b,r] @ W1[r]),              A-op = Trh/Trl (split)
// out: g_Yh/g_Yl [b,r][row][0..103] (cols 100..103 zeroed; dvec written later)
__global__ __launch_bounds__(256) void k_ygemm_tc(int mode, const float* __restrict__ uni,
                                                  const float* __restrict__ start)
{
    int r = blockIdx.x, b = blockIdx.y, z = blockIdx.z;
    int m0 = (z == 3) ? 136 : z * 64;

    const __nv_bfloat16 *Ah, *Al, *Wh, *Wl;
    if (mode == 0) {
        Ah = g_Xh + (size_t)b * NRH;  Al = g_Xl + (size_t)b * NRH;
        Wh = g_Wh + (size_t)r * HD * WW;  Wl = g_Wl + (size_t)r * HD * WW;
    } else {
        Ah = g_Trh + (size_t)(b*NH + r) * NRH;  Al = g_Trl + (size_t)(b*NH + r) * NRH;
        Wh = g_Wh + (size_t)(35 + r) * HD * WW;  Wl = g_Wl + (size_t)(35 + r) * HD * WW;
    }
    float cs = uni[b*NH + r];
    __nv_bfloat16* Oh = g_Yh + (size_t)(b*NH + r) * NN * YW;
    __nv_bfloat16* Ol = g_Yl + (size_t)(b*NH + r) * NN * YW;

    __shared__ __align__(16) __nv_bfloat16 sAh[64][24];
    __shared__ __align__(16) __nv_bfloat16 sAl[64][24];
    __shared__ __align__(16) __nv_bfloat16 sBh[16][120];
    __shared__ __align__(16) __nv_bfloat16 sBl[16][120];

    int tid = threadIdx.x, lane = tid & 31, wid = tid >> 5;
    int wm = wid & 3, wn = wid >> 2;

    float acc[7][4];
    #pragma unroll
    for (int f = 0; f < 7; ++f)
        #pragma unroll
        for (int q = 0; q < 4; ++q) acc[f][q] = 0.f;

    uint32_t aAddrH = smem_u32(&sAh[wm*16 + (lane & 15)][(lane >> 4) * 8]);
    uint32_t aAddrL = smem_u32(&sAl[wm*16 + (lane & 15)][(lane >> 4) * 8]);
    uint32_t bRowH  = smem_u32(&sBh[lane & 15][0]);
    uint32_t bRowL  = smem_u32(&sBl[lane & 15][0]);

    int ldA_row = tid >> 2, ldA_kp = (tid & 3) * 4;
    int ldB_j = tid >> 4, ldB_c = tid & 15;

    for (int c = 0; c < 7; ++c) {
        int k0 = c * 16;
        // A tiles (64 x 16), uint2 loads (8B) — element offsets always %4==0
        {
            int gi = m0 + ldA_row, gk = k0 + ldA_kp;
            uint2 vh = make_uint2(0u, 0u), vl = vh;
            if (gi < NN && gk + 3 < HD) {
                vh = *(const uint2*)(Ah + (size_t)gi * HD + gk);
                vl = *(const uint2*)(Al + (size_t)gi * HD + gk);
            }
            *(uint2*)&sAh[ldA_row][ldA_kp] = vh;
            *(uint2*)&sAl[ldA_row][ldA_kp] = vl;
        }
        // B tiles (16 x 120) from padded W [k][104]; rows are 208B -> uint4-safe
        {
            int gj = k0 + ldB_j;
            if (ldB_c <= 12) {
                uint4 vh = make_uint4(0u,0u,0u,0u), vl = vh;
                if (gj < HD) {
                    vh = *(const uint4*)(Wh + (size_t)gj * WW + ldB_c * 8);
                    vl = *(const uint4*)(Wl + (size_t)gj * WW + ldB_c * 8);
                }
                *(uint4*)&sBh[ldB_j][ldB_c*8] = vh;
                *(uint4*)&sBl[ldB_j][ldB_c*8] = vl;
            } else if (ldB_c <= 14) {
                uint4 z4 = make_uint4(0u,0u,0u,0u);
                *(uint4*)&sBh[ldB_j][ldB_c*8] = z4;
                *(uint4*)&sBl[ldB_j][ldB_c*8] = z4;
            }
        }
        __syncthreads();
        uint32_t ah0, ah1, ah2, ah3, al0, al1, al2, al3;
        ldsm_x4(ah0, ah1, ah2, ah3, aAddrH);
        ldsm_x4(al0, al1, al2, al3, aAddrL);
        #pragma unroll
        for (int f = 0; f < 7; ++f) {
            uint32_t off = (uint32_t)(wn*56 + f*8) * 2;
            uint32_t b0, b1;
            ldsm_x2t(b0, b1, bRowH + off);
            mma16816(acc[f], ah0, ah1, ah2, ah3, b0, b1);   // Xh*Wh
            mma16816(acc[f], al0, al1, al2, al3, b0, b1);   // Xl*Wh
            ldsm_x2t(b0, b1, bRowL + off);
            mma16816(acc[f], ah0, ah1, ah2, ah3, b0, b1);   // Xh*Wl
        }
        __syncthreads();
    }

    int g = lane >> 2, tg = lane & 3;
    #pragma unroll
    for (int f = 0; f < 7; ++f) {
        int nb = wn*56 + f*8;
        #pragma unroll
        for (int q = 0; q < 4; ++q) {
            int row = m0 + wm*16 + g + (q >> 1) * 8;
            int col = nb + tg*2 + (q & 1);
            if (row < NN && col < YW) {
                float v = (col < HD) ? acc[f][q] * cs * (mode == 0 ? start[b*NN + row] : 1.f) : 0.f;
                __nv_bfloat16 h = __float2bfloat16(v);
                size_t o = (size_t)row * YW + col;
                Oh[o] = h;
                Ol[o] = __float2bfloat16(v - __bfloat162float(h));
            }
        }
    }
}

// ---------------- tensor-core A GEMM: Zh = A @ [Y | dvec] ----------------
__global__ __launch_bounds__(256) void k_agemm_tc()
{
    int r = blockIdx.x, b = blockIdx.y, z = blockIdx.z;
    int m0 = (z == 3) ? 136 : z * 64;

    const __nv_bfloat16* Ab = g_Ab + (size_t)(b*NH + r) * NN * NN;
    const __nv_bfloat16* Yh = g_Yh + (size_t)(b*NH + r) * NN * YW;
    const __nv_bfloat16* Yl = g_Yl + (size_t)(b*NH + r) * NN * YW;
    float* Zb = g_Zh + (size_t)(b*NH + r) * NRH;
    float* Db = g_D + (b*NH + r) * NN;

    __shared__ __align__(16) __nv_bfloat16 sA[64][24];
    __shared__ __align__(16) __nv_bfloat16 sBh[16][120];
    __shared__ __align__(16) __nv_bfloat16 sBl[16][120];

    int tid = threadIdx.x, lane = tid & 31, wid = tid >> 5;
    int wm = wid & 3, wn = wid >> 2;

    float acc[7][4];
    #pragma unroll
    for (int f = 0; f < 7; ++f)
        #pragma unroll
        for (int q = 0; q < 4; ++q) acc[f][q] = 0.f;

    uint32_t aAddr = smem_u32(&sA[wm*16 + (lane & 15)][(lane >> 4) * 8]);
    uint32_t bRowH = smem_u32(&sBh[lane & 15][0]);
    uint32_t bRowL = smem_u32(&sBl[lane & 15][0]);

    int ldA_row = tid >> 2, ldA_kp = (tid & 3) * 4;
    int ldB_j = tid >> 4, ldB_c = tid & 15;

    for (int c = 0; c < 13; ++c) {
        int k0 = c * 16;
        // A tile 64x16 from bf16 A (width 200), uint2 loads
        {
            int gi = m0 + ldA_row, gk = k0 + ldA_kp;
            uint2 v = make_uint2(0u, 0u);
            if (gi < NN && gk + 3 < NN)
                v = *(const uint2*)(Ab + (size_t)gi * NN + gk);
            *(uint2*)&sA[ldA_row][ldA_kp] = v;
        }
        // B tile 16x120 from Yh/Yl (width 104; rows 208B -> uint4-safe)
        {
            int gj = k0 + ldB_j;
            if (ldB_c <= 12) {
                uint4 vh = make_uint4(0u,0u,0u,0u), vl = vh;
                if (gj < NN) {
                    vh = *(const uint4*)(Yh + (size_t)gj * YW + ldB_c * 8);
                    vl = *(const uint4*)(Yl + (size_t)gj * YW + ldB_c * 8);
                }
                *(uint4*)&sBh[ldB_j][ldB_c*8] = vh;
                *(uint4*)&sBl[ldB_j][ldB_c*8] = vl;
            } else if (ldB_c <= 14) {
                uint4 z4 = make_uint4(0u,0u,0u,0u);
                *(uint4*)&sBh[ldB_j][ldB_c*8] = z4;
                *(uint4*)&sBl[ldB_j][ldB_c*8] = z4;
            }
        }
        __syncthreads();
        uint32_t a0, a1, a2, a3;
        ldsm_x4(a0, a1, a2, a3, aAddr);
        #pragma unroll
        for (int f = 0; f < 7; ++f) {
            uint32_t off = (uint32_t)(wn*56 + f*8) * 2;
            uint32_t b0, b1;
            ldsm_x2t(b0, b1, bRowH + off);
            mma16816(acc[f], a0, a1, a2, a3, b0, b1);   // A*Yh
            ldsm_x2t(b0, b1, bRowL + off);
            mma16816(acc[f], a0, a1, a2, a3, b0, b1);   // A*Yl
        }
        __syncthreads();
    }

    int g = lane >> 2, tg = lane & 3;
    #pragma unroll
    for (int f = 0; f < 7; ++f) {
        int nb = wn*56 + f*8;
        #pragma unroll
        for (int q = 0; q < 4; ++q) {
            int row = m0 + wm*16 + g + (q >> 1) * 8;
            int col = nb + tg*2 + (q & 1);
            if (row < NN) {
                if (col < HD)       Zb[row*HD + col] = acc[f][q];
                else if (col == HD) Db[row] = acc[f][q];
            }
        }
    }
}

// ---------------- Zsum[b,x] = sum_r Zh0[b,r,x] ----------------
__global__ void k_rsum()
{
    int x = blockIdx.x * 256 + threadIdx.x;
    int b = blockIdx.y;
    if (x >= NRH) return;
    float acc = 0.f;
    #pragma unroll 2
    for (int r = 0; r < NH; ++r)
        acc += g_Zh[(size_t)(b*NH + r) * NRH + x];
    g_Zsum[(size_t)b * NRH + x] = acc;
}

// ---------------- Zt0 = rowscale(end) * (Zsum[b] @ Wpad)  (SIMT, 32 CTAs) ----------------
__global__ void k_zt0(const float* __restrict__ wvs, const float* __restrict__ endv)
{
    int b = blockIdx.x;
    const float* In = g_Zsum + (size_t)b * NRH;
    const float* W = wvs + (size_t)69 * (HD*HD);   // w_vs[1,34] = W_pad[0]
    const float* rs = endv + b*NN;
    float* Out = g_Zt + (size_t)b * NRH;

    __shared__ float As[128][33];
    __shared__ float Bs[32][128];
    int tid = threadIdx.x;
    int tx = tid & 15, ty = tid >> 4;

    for (int mt = 0; mt < 2; ++mt) {
        float acc[8][8];
        #pragma unroll
        for (int i = 0; i < 8; ++i)
            #pragma unroll
            for (int j = 0; j < 8; ++j) acc[i][j] = 0.f;

        for (int k0 = 0; k0 < HD; k0 += 32) {
            int klen = min(32, HD - k0);
            #pragma unroll
            for (int l = 0; l < 4; ++l) {
                int idx = tid + l*256;
                int row = idx >> 3;
                int c4 = (idx & 7) << 2;
                int grow = mt*128 + row;
                float4 v = make_float4(0.f,0.f,0.f,0.f);
                if (grow < NN && c4 < klen)
                    v = *(const float4*)(In + (size_t)grow*HD + k0 + c4);
                As[row][c4+0] = v.x; As[row][c4+1] = v.y;
                As[row][c4+2] = v.z; As[row][c4+3] = v.w;
            }
            #pragma unroll
            for (int l = 0; l < 4; ++l) {
                int idx = tid + l*256;
                int kk = idx >> 5;
                int c4 = (idx & 31) << 2;
                float4 v = make_float4(0.f,0.f,0.f,0.f);
                if (kk < klen && c4 < HD)
                    v = *(const float4*)(W + (size_t)(k0+kk)*HD + c4);
                *(float4*)&Bs[kk][c4] = v;
            }
            __syncthreads();
            #pragma unroll 4
            for (int kk = 0; kk < klen; ++kk) {
                float a[8];
                #pragma unroll
                for (int i = 0; i < 8; ++i) a[i] = As[ty*8 + i][kk];
                float4 b0 = *(float4*)&Bs[kk][tx*8];
                float4 b1 = *(float4*)&Bs[kk][tx*8 + 4];
                float bb[8] = {b0.x,b0.y,b0.z,b0.w,b1.x,b1.y,b1.z,b1.w};
                #pragma unroll
                for (int i = 0; i < 8; ++i)
                    #pragma unroll
                    for (int j = 0; j < 8; ++j)
                        acc[i][j] += a[i] * bb[j];
            }
            __syncthreads();
        }
        #pragma unroll
        for (int i = 0; i < 8; ++i) {
            int grow = mt*128 + ty*8 + i;
            if (grow < NN) {
                float sc = rs[grow];
                #pragma unroll
                for (int j = 0; j < 8; ++j) {
                    int c = tx*8 + j;
                    if (c < HD) Out[(size_t)grow*HD + c] = acc[i][j] * sc;
                }
            }
        }
    }
}

// ---------------- Ztr (split bf16): Trh/Trl[b,s,x] = split(sum_r Zh0[b,r,x]*trans[b,r,s]) ----------------
__global__ void k_trans(const float* __restrict__ trans)
{
    int b = blockIdx.y;
    __shared__ float ts[NH*NH];
    for (int i = threadIdx.x; i < NH*NH; i += 256) ts[i] = trans[b*NH*NH + i];
    __syncthreads();

    int x0 = blockIdx.x * 512 + threadIdx.x;
    const float* Zb = g_Zh + (size_t)b * NH * NRH;
    float acc0[NH], acc1[NH];
    #pragma unroll
    for (int s = 0; s < NH; ++s) { acc0[s] = 0.f; acc1[s] = 0.f; }

    for (int r = 0; r < NH; ++r) {
        float v0 = (x0 < NRH)       ? Zb[(size_t)r*NRH + x0]       : 0.f;
        float v1 = (x0 + 256 < NRH) ? Zb[(size_t)r*NRH + x0 + 256] : 0.f;
        #pragma unroll
        for (int s = 0; s < NH; ++s) {
            float tv = ts[r*NH + s];
            acc0[s] += v0 * tv;
            acc1[s] += v1 * tv;
        }
    }
    #pragma unroll
    for (int s = 0; s < NH; ++s) {
        size_t ob = (size_t)(b*NH + s) * NRH;
        if (x0 < NRH) {
            float v = acc0[s];
            __nv_bfloat16 h = __float2bfloat16(v);
            g_Trh[ob + x0] = h;
            g_Trl[ob + x0] = __float2bfloat16(v - __bfloat162float(h));
        }
        if (x0 + 256 < NRH) {
            float v = acc1[s];
            __nv_bfloat16 h = __float2bfloat16(v);
            g_Trh[ob + x0 + 256] = h;
            g_Trl[ob + x0 + 256] = __float2bfloat16(v - __bfloat162float(h));
        }
    }
}

// ---------------- Zt1[b,x] = end[b,i] * sum_r Zh1[b,r,x] ----------------
__global__ void k_zt1(const float* __restrict__ endv)
{
    int x = blockIdx.x * 256 + threadIdx.x;
    int b = blockIdx.y;
    if (x >= NRH) return;
    float acc = 0.f;
    #pragma unroll 2
    for (int r = 0; r < NH; ++r)
        acc += g_Zh[(size_t)(b*NH + r) * NRH + x];
    int i = x / HD;
    g_Zt[(size_t)(BS + b) * NRH + x] = acc * endv[b*NN + i];
}

// ---------------- Dt[t][b,i] = end * sum_r D[b,r,i] ----------------
__global__ void k_dt(int t, const float* __restrict__ endv)
{
    int idx = blockIdx.x * 256 + threadIdx.x;
    if (idx >= BS*NN) return;
    int b = idx / NN, i = idx - b*NN;
    float acc = 0.f;
    #pragma unroll 2
    for (int r = 0; r < NH; ++r) acc += g_D[(b*NH + r)*NN + i];
    g_Dt[t*BS*NN + idx] = acc * endv[idx];
}

// ---------------- epilogue: normalize, attn, softmax(K=2), combine ----------------
__global__ void k_out(float* __restrict__ out)
{
    int bn = blockIdx.x;
    int b = bn / NN, n = bn - b*NN;
    int tid = threadIdx.x;
    __shared__ float red[128];

    float z[2], dt[2];
    #pragma unroll
    for (int t = 0; t < 2; ++t) {
        float zv = 0.f;
        if (tid < HD) {
            float dd = g_Dt[t*BS*NN + b*NN + n];
            zv = g_Zt[(size_t)(t*BS + b) * NRH + n*HD + tid] / (dd + EPSV);
        }
        z[t] = zv;
        red[tid] = (tid < HD) ? g_Sq[b*HD + tid] * zv : 0.f;
        __syncthreads();
        for (int s = 64; s > 0; s >>= 1) {
            if (tid < s) red[tid] += red[tid + s];
            __syncthreads();
        }
        dt[t] = red[0] * 0.1f;   // / sqrt(100)
        __syncthreads();
    }
    float m = fmaxf(dt[0], dt[1]);
    float e0 = expf(dt[0] - m), e1 = expf(dt[1] - m);
    float inv = 1.f / (e0 + e1);
    if (tid < HD)
        out[(size_t)bn * HD + tid] = (e0 * z[0] + e1 * z[1]) * inv;
}

// ---------------- launch ----------------
extern "C" void kernel_launch(void* const* d_in, const int* in_sizes, int n_in,
                              void* d_out, int out_size)
{
    (void)in_sizes; (void)n_in; (void)out_size;
    const float* X     = (const float*)d_in[0];
    const float* A     = (const float*)d_in[1];
    const float* start = (const float*)d_in[2];
    const float* endv  = (const float*)d_in[3];
    const float* uni   = (const float*)d_in[4];
    const float* trans = (const float*)d_in[5];
    const float* S     = (const float*)d_in[6];
    const float* wvs   = (const float*)d_in[7];
    const float* wqw   = (const float*)d_in[8];
    const float* wqb   = (const float*)d_in[9];
    float* out = (float*)d_out;

    // conversions
    k_sq<<<(BS*HD + 7) / 8, 256>>>(S, wqw, wqb);
    k_convA<<<42500, 256>>>(A);                        // 43.52M elems / 4 per thread
    k_splitX<<<(BS*NRH + 255)/256, 256>>>(X, BS*NRH);
    k_splitW<<<(70*HD*WW + 255)/256, 256>>>(wvs);

    dim3 gg(NH, BS, 4);
    // t = 0
    k_ygemm_tc<<<gg, 256>>>(0, uni, start);            // Y0 (split bf16)
    k_dvec0b<<<(BS*NH*NN + 255)/256, 256>>>(start, uni);
    k_agemm_tc<<<gg, 256>>>();                         // Zh0, D0
    k_dt<<<(BS*NN + 255)/256, 256>>>(0, endv);
    k_rsum<<<dim3((NRH + 255)/256, BS), 256>>>();
    k_zt0<<<BS, 256>>>(wvs, endv);
    k_trans<<<dim3((NRH + 511)/512, BS), 256>>>(trans);
    // t = 1
    k_ygemm_tc<<<gg, 256>>>(1, uni, start);            // Y1
    k_dvec1b<<<(BS*NH*NN + 255)/256, 256>>>(uni, trans);
    k_agemm_tc<<<gg, 256>>>();                         // Zh1, D1
    k_dt<<<(BS*NN + 255)/256, 256>>>(1, endv);
    k_zt1<<<dim3((NRH + 255)/256, BS), 256>>>(endv);
    // epilogue
    k_out<<<BS*NN, 128>>>(out);
}